// round 10
// baseline (speedup 1.0000x reference)
#include <cuda_runtime.h>
#include <cuda_fp16.h>
#include <cstdint>

#define Bsz 4
#define Nseq 2048
#define Cdim 768
#define Hn 12
#define Dh 64
#define Mtot 8192
#define QKVN 2304
#define SCALEF 0.125f
#define LOG2E 1.4426950408889634f

// fp16 scratch (allocation-guard-safe __device__ globals)
__device__ __half g_xh[(size_t)Mtot * Cdim];
__device__ __half g_wqh[(size_t)QKVN * Cdim];
__device__ __half g_wph[(size_t)Cdim * Cdim];
__device__ __half g_qh[(size_t)Bsz * Hn * Nseq * Dh];  // [B,H,N,D], scaled 0.125*log2e
__device__ __half g_kh[(size_t)Bsz * Hn * Nseq * Dh];
__device__ __half g_vh[(size_t)Bsz * Hn * Nseq * Dh];
__device__ __half g_aoh[(size_t)Mtot * Cdim];

// ---------------- PTX helpers ----------------
__device__ __forceinline__ uint32_t smem_u32(const void* p) {
    uint32_t a;
    asm("{ .reg .u64 t; cvta.to.shared.u64 t, %1; cvt.u32.u64 %0, t; }"
        : "=r"(a) : "l"(p));
    return a;
}
__device__ __forceinline__ uint32_t h2ex2(uint32_t x) {
    uint32_t y;
    asm("ex2.approx.f16x2 %0, %1;" : "=r"(y) : "r"(x));
    return y;
}

#define CP16(saddr, gptr) \
    asm volatile("cp.async.cg.shared.global [%0], [%1], 16;" \
                 :: "r"(saddr), "l"(gptr) : "memory")
#define CP_COMMIT() asm volatile("cp.async.commit_group;" ::: "memory")
#define CP_WAIT0()  asm volatile("cp.async.wait_group 0;" ::: "memory")

#define LDM_X4(r, addr) \
    asm volatile("ldmatrix.sync.aligned.m8n8.x4.shared.b16 {%0,%1,%2,%3}, [%4];" \
        : "=r"((r)[0]), "=r"((r)[1]), "=r"((r)[2]), "=r"((r)[3]) : "r"(addr))
#define LDM_X4_T(r, addr) \
    asm volatile("ldmatrix.sync.aligned.m8n8.x4.trans.shared.b16 {%0,%1,%2,%3}, [%4];" \
        : "=r"((r)[0]), "=r"((r)[1]), "=r"((r)[2]), "=r"((r)[3]) : "r"(addr))
#define LDM_X2_T(r, addr) \
    asm volatile("ldmatrix.sync.aligned.m8n8.x2.trans.shared.b16 {%0,%1}, [%2];" \
        : "=r"((r)[0]), "=r"((r)[1]) : "r"(addr))

#define MMA(c, a, b0, b1) \
    asm volatile("mma.sync.aligned.m16n8k16.row.col.f32.f16.f16.f32 " \
        "{%0,%1,%2,%3}, {%4,%5,%6,%7}, {%8,%9}, {%0,%1,%2,%3};" \
        : "+f"((c)[0]), "+f"((c)[1]), "+f"((c)[2]), "+f"((c)[3]) \
        : "r"((a)[0]), "r"((a)[1]), "r"((a)[2]), "r"((a)[3]), "r"(b0), "r"(b1))

__device__ __forceinline__ uint32_t packh2(float a, float b) {
    __half2 h = __floats2half2_rn(a, b);
    return *reinterpret_cast<uint32_t*>(&h);
}

// ---------------- fused conversion (one launch) ----------------
#define CVT_N0 (Mtot * Cdim / 4)
#define CVT_N1 (QKVN * Cdim / 4)
#define CVT_N2 (Cdim * Cdim / 4)
__global__ void cvt_all(const float* __restrict__ x, const float* __restrict__ wq,
                        const float* __restrict__ wp) {
    int i = blockIdx.x * blockDim.x + threadIdx.x;
    const float* s;
    __half* d;
    int j;
    if (i < CVT_N0) { s = x; d = g_xh; j = i; }
    else if (i < CVT_N0 + CVT_N1) { s = wq; d = g_wqh; j = i - CVT_N0; }
    else if (i < CVT_N0 + CVT_N1 + CVT_N2) { s = wp; d = g_wph; j = i - CVT_N0 - CVT_N1; }
    else return;
    float4 v = ((const float4*)s)[j];
    __half2* o = (__half2*)d;
    o[2 * j + 0] = __floats2half2_rn(v.x, v.y);
    o[2 * j + 1] = __floats2half2_rn(v.z, v.w);
}

// ---------------- HMMA GEMM: 4 warps, 64x64 warp tile, BK=64 ---------------
// D[m][o] = sum_k A[m][k]*W[o][k]. CTA tile 128x128, BK=64, 128 threads.
// Double-buffered cp.async; 12 stages -> 12 syncs (half of BK=32).
#define GSTAGE 9216   // halfs per stage per operand: 128 rows * 72
template <int EPI>
__global__ __launch_bounds__(128, 2) void tc_gemm(const float* __restrict__ bias,
                                                  float* __restrict__ out) {
    extern __shared__ __align__(16) __half gsm[];
    __half* sA = gsm;                  // [2][128*72]
    __half* sB = gsm + 2 * GSTAGE;     // [2][128*72]

    const __half* A = (EPI == 0) ? g_xh : g_aoh;
    const __half* W = (EPI == 0) ? g_wqh : g_wph;
    const int K = Cdim, NS = Cdim / 64;  // 12

    int tid = threadIdx.x, lane = tid & 31, wid = tid >> 5;
    int wm = wid >> 1, wn = wid & 1;
    int g = lane >> 2, t4 = lane & 3;
    int m0 = blockIdx.x * 128, n0 = blockIdx.y * 128;
    uint32_t sAu = smem_u32(sA), sBu = smem_u32(sB);

    float acc[4][8][4] = {};

    // stage load: 128 rows x 64 halfs per operand = 1024 16B-chunks, 8/thread
    // idx = c*128 + tid: r = idx>>3, kc = (idx&7)*8
    {
        #pragma unroll
        for (int c = 0; c < 8; c++) {
            int idx = c * 128 + tid;
            int r = idx >> 3, kc = (idx & 7) * 8;
            uint32_t so = (uint32_t)(r * 72 + kc) * 2;
            CP16(sAu + so, A + (size_t)(m0 + r) * K + kc);
            CP16(sBu + so, W + (size_t)(n0 + r) * K + kc);
        }
        CP_COMMIT();
    }

    int arow = lane & 15, ak = (lane >> 4) * 8;
    int brow = (lane & 7) + (lane >> 4) * 8;
    int bk = ((lane >> 3) & 1) * 8;

    for (int s = 0; s < NS; s++) {
        int buf = s & 1;
        CP_WAIT0();          // stage s resident
        __syncthreads();     // all warps done with buffer we're about to fill
        if (s + 1 < NS) {
            int k0 = (s + 1) * 64;
            uint32_t bo = (uint32_t)(buf ^ 1) * (GSTAGE * 2);
            #pragma unroll
            for (int c = 0; c < 8; c++) {
                int idx = c * 128 + tid;
                int r = idx >> 3, kc = (idx & 7) * 8;
                uint32_t so = bo + (uint32_t)(r * 72 + kc) * 2;
                CP16(sAu + so, A + (size_t)(m0 + r) * K + k0 + kc);
                CP16(sBu + so, W + (size_t)(n0 + r) * K + k0 + kc);
            }
            CP_COMMIT();
        }

        uint32_t sAb = sAu + (uint32_t)buf * (GSTAGE * 2);
        uint32_t sBb = sBu + (uint32_t)buf * (GSTAGE * 2);
        #pragma unroll
        for (int ks = 0; ks < 4; ks++) {
            uint32_t a[4][4], bf[4][4];
            #pragma unroll
            for (int mt = 0; mt < 4; mt++)
                LDM_X4(a[mt], sAb + (uint32_t)((wm * 64 + mt * 16 + arow) * 72
                                               + ks * 16 + ak) * 2);
            #pragma unroll
            for (int p = 0; p < 4; p++)
                LDM_X4(bf[p], sBb + (uint32_t)((wn * 64 + p * 16 + brow) * 72
                                               + ks * 16 + bk) * 2);
            #pragma unroll
            for (int mt = 0; mt < 4; mt++)
                #pragma unroll
                for (int nt = 0; nt < 8; nt++)
                    MMA(acc[mt][nt], a[mt], bf[nt >> 1][(nt & 1) * 2],
                        bf[nt >> 1][(nt & 1) * 2 + 1]);
        }
    }

    #pragma unroll
    for (int mt = 0; mt < 4; mt++) {
        #pragma unroll
        for (int nt = 0; nt < 8; nt++) {
            int row = m0 + wm * 64 + mt * 16 + g;
            int col = n0 + wn * 64 + nt * 8 + t4 * 2;
            if (EPI == 0) {
                int three = col / Cdim;
                int rem = col - three * Cdim;
                int hh = rem >> 6, d = rem & 63;
                __half* dst = (three == 0) ? g_qh : (three == 1) ? g_kh : g_vh;
                float sc = (three == 0) ? SCALEF * LOG2E : 1.0f;
                #pragma unroll
                for (int hi = 0; hi < 2; hi++) {
                    int r = row + hi * 8;
                    int bb = r >> 11, n = r & 2047;
                    size_t idx = (((size_t)(bb * Hn + hh)) * Nseq + n) * Dh + d;
                    *(__half2*)(dst + idx) = __floats2half2_rn(
                        acc[mt][nt][hi * 2] * sc, acc[mt][nt][hi * 2 + 1] * sc);
                }
            } else {
                float b0 = bias[col], b1 = bias[col + 1];
                #pragma unroll
                for (int hi = 0; hi < 2; hi++) {
                    int r = row + hi * 8;
                    float2 v = make_float2(acc[mt][nt][hi * 2] + b0,
                                           acc[mt][nt][hi * 2 + 1] + b1);
                    *(float2*)(out + (size_t)r * Cdim + col) = v;
                }
            }
        }
    }
}

// ---------------- FA2 HMMA attention: warp = 32 q-rows (proven R9) ---------
__global__ __launch_bounds__(128, 2) void tc_attn() {
    extern __shared__ __align__(16) char sm[];
    __half* Qs = (__half*)sm;               // [128][72]
    __half* Ks = Qs + 128 * 72;             // [2][128][72]
    __half* Vs = Ks + 2 * 128 * 72;         // [2][128][72]; cols 64..71 ones/zeros

    int tid = threadIdx.x, lane = tid & 31, wid = tid >> 5;
    int g = lane >> 2, t4 = lane & 3;
    int q0 = blockIdx.x * 128, h = blockIdx.y, b = blockIdx.z;
    int wr0 = wid * 32;

    size_t ho = ((size_t)(b * Hn + h)) * Nseq * Dh;
    const __half* Qp = g_qh + ho;
    const __half* Kp = g_kh + ho;
    const __half* Vp = g_vh + ho;
    uint32_t Qu = smem_u32(Qs), Ku = smem_u32(Ks), Vu = smem_u32(Vs);

    #pragma unroll
    for (int c = 0; c < 8; c++) {
        int idx = c * 128 + tid;
        int r = idx >> 3, cc = (idx & 7) * 8;
        CP16(Qu + (uint32_t)(r * 72 + cc) * 2, Qp + (size_t)(q0 + r) * Dh + cc);
        CP16(Ku + (uint32_t)(r * 72 + cc) * 2, Kp + (size_t)r * Dh + cc);
        CP16(Vu + (uint32_t)(r * 72 + cc) * 2, Vp + (size_t)r * Dh + cc);
    }
    CP_COMMIT();
    {
        uint4 ones = make_uint4(0x00003C00u, 0u, 0u, 0u);
        *(uint4*)(Vs + (size_t)tid * 72 + 64) = ones;
        *(uint4*)(Vs + (size_t)(tid + 128) * 72 + 64) = ones;
    }
    CP_WAIT0();
    __syncthreads();

    uint32_t qf[2][4][4];
    {
        int arow = lane & 15, ah = (lane >> 4) * 8;
        #pragma unroll
        for (int mt = 0; mt < 2; mt++)
            #pragma unroll
            for (int ks = 0; ks < 4; ks++)
                LDM_X4(qf[mt][ks], Qu + (uint32_t)((wr0 + mt * 16 + arow) * 72
                                                   + ks * 16 + ah) * 2);
    }

    float oacc[2][8][4] = {};
    float oaccl[2][4] = {};
    const int NKT = Nseq / 128;  // 16

    int brow = (lane & 7) + (lane >> 4) * 8;
    int bh = ((lane >> 3) & 1) * 8;
    int vrow0 = lane & 15, vh = (lane >> 4) * 8;

    for (int kt = 0; kt < NKT; kt++) {
        int buf = kt & 1;
        uint32_t Kb = Ku + (uint32_t)buf * (128 * 72 * 2);
        uint32_t Vb = Vu + (uint32_t)buf * (128 * 72 * 2);
        if (kt + 1 < NKT) {
            uint32_t Kn = Ku + (uint32_t)(buf ^ 1) * (128 * 72 * 2);
            uint32_t Vn = Vu + (uint32_t)(buf ^ 1) * (128 * 72 * 2);
            const __half* Kg = Kp + (size_t)(kt + 1) * 128 * Dh;
            const __half* Vg = Vp + (size_t)(kt + 1) * 128 * Dh;
            #pragma unroll
            for (int c = 0; c < 8; c++) {
                int idx = c * 128 + tid;
                int r = idx >> 3, cc = (idx & 7) * 8;
                CP16(Kn + (uint32_t)(r * 72 + cc) * 2, Kg + (size_t)r * Dh + cc);
                CP16(Vn + (uint32_t)(r * 72 + cc) * 2, Vg + (size_t)r * Dh + cc);
            }
            CP_COMMIT();
        }

        #pragma unroll
        for (int c = 0; c < 4; c++) {
            float sacc[2][4][4] = {};
            #pragma unroll
            for (int ks = 0; ks < 4; ks++) {
                #pragma unroll
                for (int p = 0; p < 2; p++) {
                    uint32_t bf[4];
                    LDM_X4(bf, Kb + (uint32_t)((c * 32 + p * 16 + brow) * 72
                                               + ks * 16 + bh) * 2);
                    #pragma unroll
                    for (int mt = 0; mt < 2; mt++) {
                        MMA(sacc[mt][2 * p], qf[mt][ks], bf[0], bf[1]);
                        MMA(sacc[mt][2 * p + 1], qf[mt][ks], bf[2], bf[3]);
                    }
                }
            }

            uint32_t phl[2][4][2];
            #pragma unroll
            for (int mt = 0; mt < 2; mt++)
                #pragma unroll
                for (int tt = 0; tt < 4; tt++) {
                    phl[mt][tt][0] = h2ex2(packh2(sacc[mt][tt][0], sacc[mt][tt][1]));
                    phl[mt][tt][1] = h2ex2(packh2(sacc[mt][tt][2], sacc[mt][tt][3]));
                }

            #pragma unroll
            for (int jj = 0; jj < 2; jj++) {
                uint32_t af[2][4];
                #pragma unroll
                for (int mt = 0; mt < 2; mt++) {
                    af[mt][0] = phl[mt][2 * jj][0];
                    af[mt][1] = phl[mt][2 * jj][1];
                    af[mt][2] = phl[mt][2 * jj + 1][0];
                    af[mt][3] = phl[mt][2 * jj + 1][1];
                }
                #pragma unroll
                for (int p = 0; p < 4; p++) {
                    uint32_t bv[4];
                    LDM_X4_T(bv, Vb + (uint32_t)((c * 32 + jj * 16 + vrow0) * 72
                                                 + p * 16 + vh) * 2);
                    #pragma unroll
                    for (int mt = 0; mt < 2; mt++) {
                        MMA(oacc[mt][2 * p], af[mt], bv[0], bv[1]);
                        MMA(oacc[mt][2 * p + 1], af[mt], bv[2], bv[3]);
                    }
                }
                uint32_t ov[2];
                LDM_X2_T(ov, Vb + (uint32_t)((c * 32 + jj * 16 + (lane & 15)) * 72
                                             + 64) * 2);
                #pragma unroll
                for (int mt = 0; mt < 2; mt++)
                    MMA(oaccl[mt], af[mt], ov[0], ov[1]);
            }
        }

        if (kt + 1 < NKT) CP_WAIT0();
        __syncthreads();
    }

    #pragma unroll
    for (int mt = 0; mt < 2; mt++) {
        float rsum0 = __shfl_sync(0xFFFFFFFFu, oaccl[mt][0], lane & ~3);
        float rsum1 = __shfl_sync(0xFFFFFFFFu, oaccl[mt][2], lane & ~3);
        float inv0 = 1.0f / rsum0, inv1 = 1.0f / rsum1;

        __half* ob = g_aoh + ((size_t)(b * Nseq + q0 + wr0 + mt * 16)) * Cdim + h * Dh;
        #pragma unroll
        for (int t = 0; t < 8; t++) {
            int col = (t >> 1) * 16 + (t & 1) * 8 + 2 * t4;
            *(__half2*)(ob + (size_t)g * Cdim + col) =
                __floats2half2_rn(oacc[mt][t][0] * inv0, oacc[mt][t][1] * inv0);
            *(__half2*)(ob + (size_t)(g + 8) * Cdim + col) =
                __floats2half2_rn(oacc[mt][t][2] * inv1, oacc[mt][t][3] * inv1);
        }
    }
}

// ---------------- launch ----------------
extern "C" void kernel_launch(void* const* d_in, const int* in_sizes, int n_in,
                              void* d_out, int out_size) {
    const float* x      = (const float*)d_in[0];
    const float* w_qkv  = (const float*)d_in[1];
    const float* w_proj = (const float*)d_in[2];
    const float* b_proj = (const float*)d_in[3];
    float* out = (float*)d_out;

    int cvt_tot = CVT_N0 + CVT_N1 + CVT_N2;
    cvt_all<<<(cvt_tot + 255) / 256, 256>>>(x, w_qkv, w_proj);

    const int gemm_smem = 2 * GSTAGE * 2 * 2 * 2;  // 2 ops * 2 bufs * 9216 halfs = 73728B
    cudaFuncSetAttribute(tc_gemm<0>, cudaFuncAttributeMaxDynamicSharedMemorySize, gemm_smem);
    cudaFuncSetAttribute(tc_gemm<1>, cudaFuncAttributeMaxDynamicSharedMemorySize, gemm_smem);
    tc_gemm<0><<<dim3(Mtot / 128, QKVN / 128), 128, gemm_smem>>>(nullptr, nullptr);

    const int attn_smem = 128 * 72 * 2 + 2 * (2 * 128 * 72 * 2);  // 92160
    cudaFuncSetAttribute(tc_attn, cudaFuncAttributeMaxDynamicSharedMemorySize, attn_smem);
    tc_attn<<<dim3(Nseq / 128, Hn, Bsz), 128, attn_smem>>>();

    tc_gemm<1><<<dim3(Mtot / 128, Cdim / 128), 128, gemm_smem>>>(b_proj, out);
}

// round 11
// speedup vs baseline: 1.1146x; 1.1146x over previous
#include <cuda_runtime.h>
#include <cuda_fp16.h>
#include <cstdint>

#define Bsz 4
#define Nseq 2048
#define Cdim 768
#define Hn 12
#define Dh 64
#define Mtot 8192
#define QKVN 2304
#define SCALEF 0.125f
#define LOG2E 1.4426950408889634f

// fp16 scratch (allocation-guard-safe __device__ globals)
__device__ __half g_xh[(size_t)Mtot * Cdim];
__device__ __half g_wqh[(size_t)QKVN * Cdim];
__device__ __half g_wph[(size_t)Cdim * Cdim];
__device__ __half g_qh[(size_t)Bsz * Hn * Nseq * Dh];  // [B,H,N,D], scaled 0.125*log2e
__device__ __half g_kh[(size_t)Bsz * Hn * Nseq * Dh];
__device__ __half g_vh[(size_t)Bsz * Hn * Nseq * Dh];
__device__ __half g_aoh[(size_t)Mtot * Cdim];

// ---------------- PTX helpers ----------------
__device__ __forceinline__ uint32_t smem_u32(const void* p) {
    uint32_t a;
    asm("{ .reg .u64 t; cvta.to.shared.u64 t, %1; cvt.u32.u64 %0, t; }"
        : "=r"(a) : "l"(p));
    return a;
}
__device__ __forceinline__ uint32_t h2ex2(uint32_t x) {
    uint32_t y;
    asm("ex2.approx.f16x2 %0, %1;" : "=r"(y) : "r"(x));
    return y;
}

#define CP16(saddr, gptr) \
    asm volatile("cp.async.cg.shared.global [%0], [%1], 16;" \
                 :: "r"(saddr), "l"(gptr) : "memory")
#define CP_COMMIT() asm volatile("cp.async.commit_group;" ::: "memory")
#define CP_WAIT0()  asm volatile("cp.async.wait_group 0;" ::: "memory")

#define LDM_X4(r, addr) \
    asm volatile("ldmatrix.sync.aligned.m8n8.x4.shared.b16 {%0,%1,%2,%3}, [%4];" \
        : "=r"((r)[0]), "=r"((r)[1]), "=r"((r)[2]), "=r"((r)[3]) : "r"(addr))
#define LDM_X4_T(r, addr) \
    asm volatile("ldmatrix.sync.aligned.m8n8.x4.trans.shared.b16 {%0,%1,%2,%3}, [%4];" \
        : "=r"((r)[0]), "=r"((r)[1]), "=r"((r)[2]), "=r"((r)[3]) : "r"(addr))
#define LDM_X2_T(r, addr) \
    asm volatile("ldmatrix.sync.aligned.m8n8.x2.trans.shared.b16 {%0,%1}, [%2];" \
        : "=r"((r)[0]), "=r"((r)[1]) : "r"(addr))

#define MMA(c, a, b0, b1) \
    asm volatile("mma.sync.aligned.m16n8k16.row.col.f32.f16.f16.f32 " \
        "{%0,%1,%2,%3}, {%4,%5,%6,%7}, {%8,%9}, {%0,%1,%2,%3};" \
        : "+f"((c)[0]), "+f"((c)[1]), "+f"((c)[2]), "+f"((c)[3]) \
        : "r"((a)[0]), "r"((a)[1]), "r"((a)[2]), "r"((a)[3]), "r"(b0), "r"(b1))

__device__ __forceinline__ uint32_t packh2(float a, float b) {
    __half2 h = __floats2half2_rn(a, b);
    return *reinterpret_cast<uint32_t*>(&h);
}

// ---------------- fused conversion (one launch) ----------------
#define CVT_N0 (Mtot * Cdim / 4)
#define CVT_N1 (QKVN * Cdim / 4)
#define CVT_N2 (Cdim * Cdim / 4)
__global__ void cvt_all(const float* __restrict__ x, const float* __restrict__ wq,
                        const float* __restrict__ wp) {
    int i = blockIdx.x * blockDim.x + threadIdx.x;
    const float* s;
    __half* d;
    int j;
    if (i < CVT_N0) { s = x; d = g_xh; j = i; }
    else if (i < CVT_N0 + CVT_N1) { s = wq; d = g_wqh; j = i - CVT_N0; }
    else if (i < CVT_N0 + CVT_N1 + CVT_N2) { s = wp; d = g_wph; j = i - CVT_N0 - CVT_N1; }
    else return;
    float4 v = ((const float4*)s)[j];
    __half2* o = (__half2*)d;
    o[2 * j + 0] = __floats2half2_rn(v.x, v.y);
    o[2 * j + 1] = __floats2half2_rn(v.z, v.w);
}

// ---------------- HMMA GEMM: 8 warps, 32x64 warp tile, BK=64, 2-stage ------
// D[m][o] = sum_k A[m][k]*W[o][k]. CTA tile 128x128, 256 threads.
// Low-register layout (acc 64 regs) -> 2 CTAs/SM with 12 sync points.
#define GSTAGE 9216   // halfs per stage per operand: 128 rows * 72
template <int EPI>
__global__ __launch_bounds__(256, 2) void tc_gemm(const float* __restrict__ bias,
                                                  float* __restrict__ out) {
    extern __shared__ __align__(16) __half gsm[];
    __half* sA = gsm;                  // [2][128*72]
    __half* sB = gsm + 2 * GSTAGE;     // [2][128*72]

    const __half* A = (EPI == 0) ? g_xh : g_aoh;
    const __half* W = (EPI == 0) ? g_wqh : g_wph;
    const int K = Cdim, NS = Cdim / 64;  // 12

    int tid = threadIdx.x, lane = tid & 31, wid = tid >> 5;
    int wm = wid >> 1, wn = wid & 1;
    int g = lane >> 2, t4 = lane & 3;
    int m0 = blockIdx.x * 128, n0 = blockIdx.y * 128;
    uint32_t sAu = smem_u32(sA), sBu = smem_u32(sB);

    float acc[2][8][4] = {};

    // stage load: 128 rows x 64 halfs = 1024 16B-chunks per operand, 4/thread
    {
        #pragma unroll
        for (int c = 0; c < 4; c++) {
            int idx = c * 256 + tid;
            int r = idx >> 3, kc = (idx & 7) * 8;
            uint32_t so = (uint32_t)(r * 72 + kc) * 2;
            CP16(sAu + so, A + (size_t)(m0 + r) * K + kc);
            CP16(sBu + so, W + (size_t)(n0 + r) * K + kc);
        }
        CP_COMMIT();
    }

    int arow = lane & 15, ak = (lane >> 4) * 8;
    int brow = (lane & 7) + (lane >> 4) * 8;
    int bk = ((lane >> 3) & 1) * 8;

    for (int s = 0; s < NS; s++) {
        int buf = s & 1;
        CP_WAIT0();          // stage s resident
        __syncthreads();
        if (s + 1 < NS) {
            int k0 = (s + 1) * 64;
            uint32_t bo = (uint32_t)(buf ^ 1) * (GSTAGE * 2);
            #pragma unroll
            for (int c = 0; c < 4; c++) {
                int idx = c * 256 + tid;
                int r = idx >> 3, kc = (idx & 7) * 8;
                uint32_t so = bo + (uint32_t)(r * 72 + kc) * 2;
                CP16(sAu + so, A + (size_t)(m0 + r) * K + k0 + kc);
                CP16(sBu + so, W + (size_t)(n0 + r) * K + k0 + kc);
            }
            CP_COMMIT();
        }

        uint32_t sAb = sAu + (uint32_t)buf * (GSTAGE * 2);
        uint32_t sBb = sBu + (uint32_t)buf * (GSTAGE * 2);
        #pragma unroll
        for (int ks = 0; ks < 4; ks++) {
            uint32_t a[2][4], bf[4][4];
            #pragma unroll
            for (int mt = 0; mt < 2; mt++)
                LDM_X4(a[mt], sAb + (uint32_t)((wm * 32 + mt * 16 + arow) * 72
                                               + ks * 16 + ak) * 2);
            #pragma unroll
            for (int p = 0; p < 4; p++)
                LDM_X4(bf[p], sBb + (uint32_t)((wn * 64 + p * 16 + brow) * 72
                                               + ks * 16 + bk) * 2);
            #pragma unroll
            for (int mt = 0; mt < 2; mt++)
                #pragma unroll
                for (int nt = 0; nt < 8; nt++)
                    MMA(acc[mt][nt], a[mt], bf[nt >> 1][(nt & 1) * 2],
                        bf[nt >> 1][(nt & 1) * 2 + 1]);
        }
    }

    #pragma unroll
    for (int mt = 0; mt < 2; mt++) {
        #pragma unroll
        for (int nt = 0; nt < 8; nt++) {
            int row = m0 + wm * 32 + mt * 16 + g;
            int col = n0 + wn * 64 + nt * 8 + t4 * 2;
            if (EPI == 0) {
                int three = col / Cdim;
                int rem = col - three * Cdim;
                int hh = rem >> 6, d = rem & 63;
                __half* dst = (three == 0) ? g_qh : (three == 1) ? g_kh : g_vh;
                float sc = (three == 0) ? SCALEF * LOG2E : 1.0f;
                #pragma unroll
                for (int hi = 0; hi < 2; hi++) {
                    int r = row + hi * 8;
                    int bb = r >> 11, n = r & 2047;
                    size_t idx = (((size_t)(bb * Hn + hh)) * Nseq + n) * Dh + d;
                    *(__half2*)(dst + idx) = __floats2half2_rn(
                        acc[mt][nt][hi * 2] * sc, acc[mt][nt][hi * 2 + 1] * sc);
                }
            } else {
                float b0 = bias[col], b1 = bias[col + 1];
                #pragma unroll
                for (int hi = 0; hi < 2; hi++) {
                    int r = row + hi * 8;
                    float2 v = make_float2(acc[mt][nt][hi * 2] + b0,
                                           acc[mt][nt][hi * 2 + 1] + b1);
                    *(float2*)(out + (size_t)r * Cdim + col) = v;
                }
            }
        }
    }
}

// ---------------- FA2 HMMA attention: warp = 32 q-rows (R9 + ones hoist) ---
__global__ __launch_bounds__(128, 2) void tc_attn() {
    extern __shared__ __align__(16) char sm[];
    __half* Qs = (__half*)sm;               // [128][72]
    __half* Ks = Qs + 128 * 72;             // [2][128][72]
    __half* Vs = Ks + 2 * 128 * 72;         // [2][128][72]; cols 64..71 ones/zeros

    int tid = threadIdx.x, lane = tid & 31, wid = tid >> 5;
    int g = lane >> 2, t4 = lane & 3;
    int q0 = blockIdx.x * 128, h = blockIdx.y, b = blockIdx.z;
    int wr0 = wid * 32;

    size_t ho = ((size_t)(b * Hn + h)) * Nseq * Dh;
    const __half* Qp = g_qh + ho;
    const __half* Kp = g_kh + ho;
    const __half* Vp = g_vh + ho;
    uint32_t Qu = smem_u32(Qs), Ku = smem_u32(Ks), Vu = smem_u32(Vs);

    #pragma unroll
    for (int c = 0; c < 8; c++) {
        int idx = c * 128 + tid;
        int r = idx >> 3, cc = (idx & 7) * 8;
        CP16(Qu + (uint32_t)(r * 72 + cc) * 2, Qp + (size_t)(q0 + r) * Dh + cc);
        CP16(Ku + (uint32_t)(r * 72 + cc) * 2, Kp + (size_t)r * Dh + cc);
        CP16(Vu + (uint32_t)(r * 72 + cc) * 2, Vp + (size_t)r * Dh + cc);
    }
    CP_COMMIT();
    // ones-column init (only buffer 0 needed now; frag hoisted)
    {
        uint4 ones = make_uint4(0x00003C00u, 0u, 0u, 0u);
        *(uint4*)(Vs + (size_t)tid * 72 + 64) = ones;
    }
    CP_WAIT0();
    __syncthreads();

    uint32_t qf[2][4][4];
    {
        int arow = lane & 15, ah = (lane >> 4) * 8;
        #pragma unroll
        for (int mt = 0; mt < 2; mt++)
            #pragma unroll
            for (int ks = 0; ks < 4; ks++)
                LDM_X4(qf[mt][ks], Qu + (uint32_t)((wr0 + mt * 16 + arow) * 72
                                                   + ks * 16 + ah) * 2);
    }
    // constant ones B-fragment (all rows identical) — load once
    uint32_t ov[2];
    LDM_X2_T(ov, Vu + (uint32_t)((lane & 15) * 72 + 64) * 2);

    float oacc[2][8][4] = {};
    float oaccl[2][4] = {};
    const int NKT = Nseq / 128;  // 16

    int brow = (lane & 7) + (lane >> 4) * 8;
    int bh = ((lane >> 3) & 1) * 8;
    int vrow0 = lane & 15, vh = (lane >> 4) * 8;

    for (int kt = 0; kt < NKT; kt++) {
        int buf = kt & 1;
        uint32_t Kb = Ku + (uint32_t)buf * (128 * 72 * 2);
        uint32_t Vb = Vu + (uint32_t)buf * (128 * 72 * 2);
        if (kt + 1 < NKT) {
            uint32_t Kn = Ku + (uint32_t)(buf ^ 1) * (128 * 72 * 2);
            uint32_t Vn = Vu + (uint32_t)(buf ^ 1) * (128 * 72 * 2);
            const __half* Kg = Kp + (size_t)(kt + 1) * 128 * Dh;
            const __half* Vg = Vp + (size_t)(kt + 1) * 128 * Dh;
            #pragma unroll
            for (int c = 0; c < 8; c++) {
                int idx = c * 128 + tid;
                int r = idx >> 3, cc = (idx & 7) * 8;
                CP16(Kn + (uint32_t)(r * 72 + cc) * 2, Kg + (size_t)r * Dh + cc);
                CP16(Vn + (uint32_t)(r * 72 + cc) * 2, Vg + (size_t)r * Dh + cc);
            }
            CP_COMMIT();
        }

        #pragma unroll
        for (int c = 0; c < 4; c++) {
            float sacc[2][4][4] = {};
            #pragma unroll
            for (int ks = 0; ks < 4; ks++) {
                #pragma unroll
                for (int p = 0; p < 2; p++) {
                    uint32_t bf[4];
                    LDM_X4(bf, Kb + (uint32_t)((c * 32 + p * 16 + brow) * 72
                                               + ks * 16 + bh) * 2);
                    #pragma unroll
                    for (int mt = 0; mt < 2; mt++) {
                        MMA(sacc[mt][2 * p], qf[mt][ks], bf[0], bf[1]);
                        MMA(sacc[mt][2 * p + 1], qf[mt][ks], bf[2], bf[3]);
                    }
                }
            }

            uint32_t phl[2][4][2];
            #pragma unroll
            for (int mt = 0; mt < 2; mt++)
                #pragma unroll
                for (int tt = 0; tt < 4; tt++) {
                    phl[mt][tt][0] = h2ex2(packh2(sacc[mt][tt][0], sacc[mt][tt][1]));
                    phl[mt][tt][1] = h2ex2(packh2(sacc[mt][tt][2], sacc[mt][tt][3]));
                }

            #pragma unroll
            for (int jj = 0; jj < 2; jj++) {
                uint32_t af[2][4];
                #pragma unroll
                for (int mt = 0; mt < 2; mt++) {
                    af[mt][0] = phl[mt][2 * jj][0];
                    af[mt][1] = phl[mt][2 * jj][1];
                    af[mt][2] = phl[mt][2 * jj + 1][0];
                    af[mt][3] = phl[mt][2 * jj + 1][1];
                }
                #pragma unroll
                for (int p = 0; p < 4; p++) {
                    uint32_t bv[4];
                    LDM_X4_T(bv, Vb + (uint32_t)((c * 32 + jj * 16 + vrow0) * 72
                                                 + p * 16 + vh) * 2);
                    #pragma unroll
                    for (int mt = 0; mt < 2; mt++) {
                        MMA(oacc[mt][2 * p], af[mt], bv[0], bv[1]);
                        MMA(oacc[mt][2 * p + 1], af[mt], bv[2], bv[3]);
                    }
                }
                #pragma unroll
                for (int mt = 0; mt < 2; mt++)
                    MMA(oaccl[mt], af[mt], ov[0], ov[1]);
            }
        }

        if (kt + 1 < NKT) CP_WAIT0();
        __syncthreads();
    }

    #pragma unroll
    for (int mt = 0; mt < 2; mt++) {
        float rsum0 = __shfl_sync(0xFFFFFFFFu, oaccl[mt][0], lane & ~3);
        float rsum1 = __shfl_sync(0xFFFFFFFFu, oaccl[mt][2], lane & ~3);
        float inv0 = 1.0f / rsum0, inv1 = 1.0f / rsum1;

        __half* ob = g_aoh + ((size_t)(b * Nseq + q0 + wr0 + mt * 16)) * Cdim + h * Dh;
        #pragma unroll
        for (int t = 0; t < 8; t++) {
            int col = (t >> 1) * 16 + (t & 1) * 8 + 2 * t4;
            *(__half2*)(ob + (size_t)g * Cdim + col) =
                __floats2half2_rn(oacc[mt][t][0] * inv0, oacc[mt][t][1] * inv0);
            *(__half2*)(ob + (size_t)(g + 8) * Cdim + col) =
                __floats2half2_rn(oacc[mt][t][2] * inv1, oacc[mt][t][3] * inv1);
        }
    }
}

// ---------------- launch ----------------
extern "C" void kernel_launch(void* const* d_in, const int* in_sizes, int n_in,
                              void* d_out, int out_size) {
    const float* x      = (const float*)d_in[0];
    const float* w_qkv  = (const float*)d_in[1];
    const float* w_proj = (const float*)d_in[2];
    const float* b_proj = (const float*)d_in[3];
    float* out = (float*)d_out;

    int cvt_tot = CVT_N0 + CVT_N1 + CVT_N2;
    cvt_all<<<(cvt_tot + 255) / 256, 256>>>(x, w_qkv, w_proj);

    const int gemm_smem = 2 * GSTAGE * 2 * 2;  // 73728B
    cudaFuncSetAttribute(tc_gemm<0>, cudaFuncAttributeMaxDynamicSharedMemorySize, gemm_smem);
    cudaFuncSetAttribute(tc_gemm<1>, cudaFuncAttributeMaxDynamicSharedMemorySize, gemm_smem);
    tc_gemm<0><<<dim3(Mtot / 128, QKVN / 128), 256, gemm_smem>>>(nullptr, nullptr);

    const int attn_smem = 128 * 72 * 2 + 2 * (2 * 128 * 72 * 2);  // 92160
    cudaFuncSetAttribute(tc_attn, cudaFuncAttributeMaxDynamicSharedMemorySize, attn_smem);
    tc_attn<<<dim3(Nseq / 128, Hn, Bsz), 128, attn_smem>>>();

    tc_gemm<1><<<dim3(Mtot / 128, Cdim / 128), 256, gemm_smem>>>(b_proj, out);
}